// round 3
// baseline (speedup 1.0000x reference)
#include <cuda_runtime.h>

#ifndef M_PI_F
#define M_PI_F 3.14159265358979323846f
#endif

#define FDIM 512
#define NOUT 100
#define RB 8        // rows per warp-pair
#define PAIRS_PER_BLK 4

// Warp-PAIR per 8 rows. Each warp covers 256 of the 512 columns:
//  - weight cache 24 regs/lane (vs 48), X buffers 16 regs (vs 32)
//  - __launch_bounds__(256,4) -> ~32 warps/SM, 2x occupancy vs R2
//  - one smem exchange + named barrier per 8-row task (not per row)
//  - even warp runs circuit + float4-vectorized output writes
__global__ __launch_bounds__(256, 4)
void qnet_fused_kernel(const float* __restrict__ X,
                       const float* __restrict__ preW,
                       const float* __restrict__ preB,
                       const float* __restrict__ qp,
                       const float* __restrict__ postW,
                       const float* __restrict__ postB,
                       float* __restrict__ out,
                       int B)
{
    const int tid       = threadIdx.x;
    const int warpInBlk = tid >> 5;           // 0..7
    const int lane      = tid & 31;
    const int pairInBlk = warpInBlk >> 1;     // 0..3
    const int half      = warpInBlk & 1;      // which 256-col half

    const int pairG = blockIdx.x * PAIRS_PER_BLK + pairInBlk;
    const int base  = pairG * RB;
    if (base >= B) return;
    const int rows = min(RB, B - base);

    // ---- weight cache: this half's 64 float4 per weight row, 2 per lane ----
    const float4* __restrict__ w0 = reinterpret_cast<const float4*>(preW);
    const float4* __restrict__ w1 = reinterpret_cast<const float4*>(preW + FDIM);
    const float4* __restrict__ w2 = reinterpret_cast<const float4*>(preW + 2 * FDIM);
    const int col = half * 64 + lane;          // float4 index; +32 for k=1
    float4 wa[2], wb[2], wc[2];
    #pragma unroll
    for (int k = 0; k < 2; ++k) {
        const int i = col + k * 32;
        wa[k] = __ldg(w0 + i);
        wb[k] = __ldg(w1 + i);
        wc[k] = __ldg(w2 + i);
    }

    const float4* __restrict__ xr = reinterpret_cast<const float4*>(X + (size_t)base * FDIM);

    // ---- streamed dot products; lane (r&7) keeps row r's half-sums ----
    const int myrow = lane & 7;
    float a0 = 0.f, a1 = 0.f, a2 = 0.f;

    float4 x[2];
    #pragma unroll
    for (int k = 0; k < 2; ++k) x[k] = xr[col + k * 32];

    #pragma unroll
    for (int r = 0; r < RB; ++r) {
        float4 xn[2];
        if (r + 1 < rows) {
            #pragma unroll
            for (int k = 0; k < 2; ++k) xn[k] = xr[(r + 1) * 128 + col + k * 32];
        }

        float d0 = 0.f, d1 = 0.f, d2 = 0.f;
        #pragma unroll
        for (int k = 0; k < 2; ++k) {
            const float4 xv = x[k];
            d0 += xv.x * wa[k].x + xv.y * wa[k].y + xv.z * wa[k].z + xv.w * wa[k].w;
            d1 += xv.x * wb[k].x + xv.y * wb[k].y + xv.z * wb[k].z + xv.w * wb[k].w;
            d2 += xv.x * wc[k].x + xv.y * wc[k].y + xv.z * wc[k].z + xv.w * wc[k].w;
        }
        #pragma unroll
        for (int off = 16; off > 0; off >>= 1) {
            d0 += __shfl_xor_sync(0xFFFFFFFFu, d0, off);
            d1 += __shfl_xor_sync(0xFFFFFFFFu, d1, off);
            d2 += __shfl_xor_sync(0xFFFFFFFFu, d2, off);
        }
        if (myrow == r) { a0 = d0; a1 = d1; a2 = d2; }

        #pragma unroll
        for (int k = 0; k < 2; ++k) x[k] = xn[k];
    }

    // ---- cross-warp combine: odd warp publishes, one named barrier ----
    __shared__ float sp[PAIRS_PER_BLK][32];
    if (half == 1) {
        if (lane < RB) {
            sp[pairInBlk][lane * 3 + 0] = a0;
            sp[pairInBlk][lane * 3 + 1] = a1;
            sp[pairInBlk][lane * 3 + 2] = a2;
        }
    }
    asm volatile("bar.sync %0, 64;" :: "r"(1 + pairInBlk) : "memory");
    if (half == 1) return;

    a0 += sp[pairInBlk][myrow * 3 + 0];
    a1 += sp[pairInBlk][myrow * 3 + 1];
    a2 += sp[pairInBlk][myrow * 3 + 2];

    // ---- circuit: lane (r&7) simulates row r (all 8 rows in one pass) ----
    const float t0 = tanhf(a0 + __ldg(preB + 0)) * (M_PI_F * 0.5f);
    const float t1 = tanhf(a1 + __ldg(preB + 1)) * (M_PI_F * 0.5f);
    const float t2 = tanhf(a2 + __ldg(preB + 2)) * (M_PI_F * 0.5f);

    float s[8];
    const float inv_sqrt8 = 0.3535533905932738f;
    #pragma unroll
    for (int i = 0; i < 8; ++i) s[i] = inv_sqrt8;

    auto ry0 = [&](float th) {
        float sn, cs; __sincosf(th * 0.5f, &sn, &cs);
        #pragma unroll
        for (int i = 0; i < 4; ++i) {
            float a = s[i], b = s[i + 4];
            s[i]     = cs * a - sn * b;
            s[i + 4] = sn * a + cs * b;
        }
    };
    auto ry1 = [&](float th) {
        float sn, cs; __sincosf(th * 0.5f, &sn, &cs);
        #pragma unroll
        for (int g = 0; g < 2; ++g)
            #pragma unroll
            for (int i = 0; i < 2; ++i) {
                int lo = g * 4 + i;
                float a = s[lo], b = s[lo + 2];
                s[lo]     = cs * a - sn * b;
                s[lo + 2] = sn * a + cs * b;
            }
    };
    auto ry2 = [&](float th) {
        float sn, cs; __sincosf(th * 0.5f, &sn, &cs);
        #pragma unroll
        for (int g = 0; g < 4; ++g) {
            int lo = g * 2;
            float a = s[lo], b = s[lo + 1];
            s[lo]     = cs * a - sn * b;
            s[lo + 1] = sn * a + cs * b;
        }
    };

    ry0(t0); ry1(t1); ry2(t2);

    #pragma unroll
    for (int k = 0; k < 2; ++k) {
        float tmp;
        tmp = s[4]; s[4] = s[6]; s[6] = tmp;   // CNOT(0,1)
        tmp = s[5]; s[5] = s[7]; s[7] = tmp;
        tmp = s[2]; s[2] = s[3]; s[3] = tmp;   // CNOT(1,2)
        tmp = s[6]; s[6] = s[7]; s[7] = tmp;
        ry0(__ldg(qp + 3 * (k + 1) + 0));
        ry1(__ldg(qp + 3 * (k + 1) + 1));
        ry2(__ldg(qp + 3 * (k + 1) + 2));
    }

    float p[8];
    #pragma unroll
    for (int i = 0; i < 8; ++i) p[i] = s[i] * s[i];

    const float z0 = (p[0] + p[1] + p[2] + p[3]) - (p[4] + p[5] + p[6] + p[7]);
    const float z1 = (p[0] + p[1] + p[4] + p[5]) - (p[2] + p[3] + p[6] + p[7]);
    const float z2 = (p[0] + p[2] + p[4] + p[6]) - (p[1] + p[3] + p[5] + p[7]);

    // ---- post weights, float4-grouped: lane l<25 owns outputs 4l..4l+3 ----
    float pa[4], pb_[4], pc[4], pd[4];
    if (lane < 25) {
        #pragma unroll
        for (int j = 0; j < 4; ++j) {
            const int n = lane * 4 + j;
            pa[j]  = __ldg(postW + n * 3 + 0);
            pb_[j] = __ldg(postW + n * 3 + 1);
            pc[j]  = __ldg(postW + n * 3 + 2);
            pd[j]  = __ldg(postB + n);
        }
    }

    #pragma unroll
    for (int r = 0; r < RB; ++r) {
        if (r >= rows) break;
        const float zz0 = __shfl_sync(0xFFFFFFFFu, z0, r);
        const float zz1 = __shfl_sync(0xFFFFFFFFu, z1, r);
        const float zz2 = __shfl_sync(0xFFFFFFFFu, z2, r);
        if (lane < 25) {
            float4 o;
            o.x = zz0 * pa[0] + zz1 * pb_[0] + zz2 * pc[0] + pd[0];
            o.y = zz0 * pa[1] + zz1 * pb_[1] + zz2 * pc[1] + pd[1];
            o.z = zz0 * pa[2] + zz1 * pb_[2] + zz2 * pc[2] + pd[2];
            o.w = zz0 * pa[3] + zz1 * pb_[3] + zz2 * pc[3] + pd[3];
            reinterpret_cast<float4*>(out + (size_t)(base + r) * NOUT)[lane] = o;
        }
    }
}

extern "C" void kernel_launch(void* const* d_in, const int* in_sizes, int n_in,
                              void* d_out, int out_size)
{
    const float* X     = (const float*)d_in[0]; // [B, 512]
    const float* preW  = (const float*)d_in[1]; // [3, 512]
    const float* preB  = (const float*)d_in[2]; // [3]
    const float* qp    = (const float*)d_in[3]; // [45]
    const float* postW = (const float*)d_in[4]; // [100, 3]
    const float* postB = (const float*)d_in[5]; // [100]
    float* out = (float*)d_out;                 // [B, 100]

    const int B = in_sizes[0] / FDIM;
    const int pairs  = (B + RB - 1) / RB;
    const int blocks = (pairs + PAIRS_PER_BLK - 1) / PAIRS_PER_BLK;

    qnet_fused_kernel<<<blocks, 256>>>(X, preW, preB, qp, postW, postB, out, B);
}